// round 16
// baseline (speedup 1.0000x reference)
#include <cuda_runtime.h>
#include <cuda_bf16.h>
#include <math.h>

// Problem constants
#define NB   64     // batch
#define TT   512    // time steps
#define DD   512    // input dim
#define HH   512    // hidden dim
#define G4   2048   // 4*H

typedef unsigned long long u64;

// ---------------------------------------------------------------------------
// Packed f32x2 helpers (sm_103a FFMA2 — ptxas never auto-generates these)
// ---------------------------------------------------------------------------
__device__ __forceinline__ u64 pack_dup(float v)
{
    u64 r; asm("mov.b64 %0, {%1, %1};" : "=l"(r) : "f"(v)); return r;
}
__device__ __forceinline__ void ffma2(u64& acc, u64 a, u64 b)
{
    asm("fma.rn.f32x2 %0, %1, %2, %0;" : "+l"(acc) : "l"(a), "l"(b));
}
__device__ __forceinline__ float2 unpk(u64 v)
{
    float2 r; asm("mov.b64 {%0, %1}, %2;" : "=f"(r.x), "=f"(r.y) : "l"(v)); return r;
}

// ---------------------------------------------------------------------------
// Scratch (device globals: the sanctioned no-alloc workaround)
// ---------------------------------------------------------------------------
#define NCTA 128
#define FLAG_STRIDE 32   // 128B between flags -> distinct L2 lines/slices

__device__ float    g_xh[(size_t)TT * NB * G4];   // (T, N, 4H) pre-projected gates
__device__ unsigned g_flag[NCTA * FLAG_STRIDE];   // per-CTA step flags, padded

// ---------------------------------------------------------------------------
// Kernel 1: xh = x @ W_xh + (b_xh + b_hh)   — FFMA2 inner loop.
// Block (0,0) additionally zeroes the step flags.
// ---------------------------------------------------------------------------
#define BM 128
#define BN 128
#define BK 8

__global__ __launch_bounds__(256, 2)
void gemm_xh_kernel(const float* __restrict__ x,
                    const float* __restrict__ Wxh,
                    const float* __restrict__ bxh,
                    const float* __restrict__ bhh)
{
    __shared__ float As[BK][BM];   // transposed A tile
    __shared__ float Bs[BK][BN];

    const int tid = threadIdx.x;
    const int bm  = blockIdx.y;
    const int bn  = blockIdx.x;

    // flag reset folded in (keeps graph replays deterministic)
    if (bm == 0 && bn == 0) {
        for (int i = tid; i < NCTA * FLAG_STRIDE; i += 256) g_flag[i] = 0u;
    }

    const int warp = tid >> 5, lane = tid & 31;
    const int wm = warp >> 1, wn = warp & 1;
    const int tm = lane & 3,  tn = lane >> 2;
    const int m0 = wm * 32 + tm * 8;
    const int n0 = wn * 64 + tn * 8;

    const int ar = tid >> 1;
    const int aq = tid & 1;
    const int gm = bm * BM + ar;            // global row m = t*64+n
    const int t  = gm >> 6;
    const int nn = gm & 63;
    const float* __restrict__ arow = x + ((size_t)nn * TT + t) * DD;

    const int rb = tid >> 5;
    const int cb = (tid & 31) * 4;
    const float* __restrict__ bcol = Wxh + (size_t)bn * BN + cb;

    u64 acc2[8][4];
#pragma unroll
    for (int i = 0; i < 8; i++)
#pragma unroll
        for (int j = 0; j < 4; j++) acc2[i][j] = 0ull;

    for (int k0 = 0; k0 < DD; k0 += BK) {
        const float4 av = *(const float4*)(arow + k0 + aq * 4);
        const float4 bv = *(const float4*)(bcol + (size_t)(k0 + rb) * G4);
        __syncthreads();
        As[aq * 4 + 0][ar] = av.x;
        As[aq * 4 + 1][ar] = av.y;
        As[aq * 4 + 2][ar] = av.z;
        As[aq * 4 + 3][ar] = av.w;
        *(float4*)&Bs[rb][cb] = bv;
        __syncthreads();

#pragma unroll
        for (int kk = 0; kk < BK; kk++) {
            float ra[8];
            *(float4*)&ra[0] = *(const float4*)&As[kk][m0];
            *(float4*)&ra[4] = *(const float4*)&As[kk][m0 + 4];
            const ulonglong2 b01 = *(const ulonglong2*)&Bs[kk][n0];
            const ulonglong2 b23 = *(const ulonglong2*)&Bs[kk][n0 + 4];
#pragma unroll
            for (int i = 0; i < 8; i++) {
                const u64 ai = pack_dup(ra[i]);
                ffma2(acc2[i][0], ai, b01.x);
                ffma2(acc2[i][1], ai, b01.y);
                ffma2(acc2[i][2], ai, b23.x);
                ffma2(acc2[i][3], ai, b23.y);
            }
        }
    }

    const int col0 = bn * BN + n0;
    float bsum[8];
#pragma unroll
    for (int j = 0; j < 8; j++)
        bsum[j] = bxh[col0 + j] + bhh[col0 + j];

#pragma unroll
    for (int i = 0; i < 8; i++) {
        const size_t row = (size_t)(bm * BM + m0 + i);
        float* p = g_xh + row * G4 + col0;
        float2 c0 = unpk(acc2[i][0]);
        float2 c1 = unpk(acc2[i][1]);
        float2 c2 = unpk(acc2[i][2]);
        float2 c3 = unpk(acc2[i][3]);
        float4 v0 = make_float4(c0.x + bsum[0], c0.y + bsum[1],
                                c1.x + bsum[2], c1.y + bsum[3]);
        float4 v1 = make_float4(c2.x + bsum[4], c2.y + bsum[5],
                                c3.x + bsum[6], c3.y + bsum[7]);
        *(float4*)p       = v0;
        *(float4*)(p + 4) = v1;
    }
}

// ---------------------------------------------------------------------------
// Kernel 2: persistent LSTM recurrence — 32 hidden-groups x 4 batch-groups,
// warp-specialized staging with DOUBLE-BUFFERED hs.
//   warps 0-7  (256 thr): dot + activation (mapping identical to R15:
//     kh = warp>>2 k-half, 2 batches x 4 gates x 1 col per thread, FFMA2).
//   warps 8-11 (128 thr): stagers. Warp w owns producers hg in [8w, 8w+8):
//     polls those 8 flags (monotonic, gpu-scope acquire), then copies its
//     16-row x 128-col slice of h(t) from y into hs[t&1] fully coalesced
//     (16x LDG.128/lane, MLP 16), then bar.arrive 1,384.
// Dot warps issue ONE bar.sync 1,384 per step — no smem spin-polling (the
// R10 failure). Staging latency + producer skew + release visibility all
// hide under the previous step's dot. Buffer-overwrite safety: any flag
// >= t+1 in this batch group transitively implies every CTA of the group
// finished step t-1 (producers' own bar1 waited on our flag), so writing
// hs[t&1] cannot race the step-(t-1) readers of the same parity.
// Intra-dot exchange barriers use bar.sync 2,256 (dot warps only).
// ---------------------------------------------------------------------------
#define NBG  16           // batches per batch-group
#define WSL  516          // per-slice stride (512 + 4 floats)
#define HSL  516          // per-h-row stride
#define KHALF 256         // k per warp-half
#define NTH  384          // 8 dot warps + 4 stager warps

#define SM_W   (64 * WSL)                 // 33024 floats
#define SM_H1  (NBG * HSL)                // 8256 floats (one h buffer)
#define SM_R   (256 * 5)                  // 1280 (partial-exchange, pad 5)
#define SM_BYTES  ((SM_W + 2 * SM_H1 + SM_R) * 4)   // 203264

__device__ __forceinline__ float fsigmoid_(float v)
{
    return 1.f / (1.f + __expf(-v));
}
__device__ __forceinline__ float ftanh_(float v)
{
    return 1.f - 2.f / (1.f + __expf(2.f * v));
}

__global__ __launch_bounds__(NTH, 1)
void lstm_kernel(const float* __restrict__ Whh, float* __restrict__ y)
{
    extern __shared__ float sm[];
    float* __restrict__ wsT = sm;                        // [64 slices][WSL]
    float* __restrict__ hs  = sm + SM_W;                 // [2][NBG][HSL]
    float* __restrict__ red = sm + SM_W + 2 * SM_H1;     // [256][5]

    const int tid  = threadIdx.x;
    const int b    = blockIdx.x;
    const int bg   = b & 3;                // batch group
    const int hg   = b >> 2;               // hidden group
    const int hc0  = hg * 16;              // first h-col owned
    const int nb0  = bg * NBG;             // first batch owned
    const int warp = tid >> 5;
    const int lane = tid & 31;
    const bool is_dot = (tid < 256);

    // ---- load W_hh slices into smem: slice p = g*16 + j, k-contiguous
    for (int i = tid; i < 64 * 512; i += NTH) {
        const int k = i & 511;
        const int p = i >> 9;              // 0..63
        const int g = p >> 4;              // gate type
        const int j = p & 15;              // local h-col
        wsT[p * WSL + k] = Whh[(size_t)k * G4 + g * HH + hc0 + j];
    }

    // ---- dot mapping (meaningful for warps 0-7 only)
    const int kh  = (warp >> 2) & 1;       // k-half 0/1
    const int jq  = warp & 3;              // j quad
    const int np  = lane & 7;              // batch pair base 0..7
    const int jlo = lane >> 3;             // 0..3
    const int j   = jq * 4 + jlo;          // 0..15
    const int k0  = kh * KHALF;

    const int woff0 = (0 * 16 + j) * WSL + k0;
    const int woff1 = (1 * 16 + j) * WSL + k0;
    const int woff2 = (2 * 16 + j) * WSL + k0;
    const int woff3 = (3 * 16 + j) * WSL + k0;

    // ---- activation assignment: this thread owns (n_act, j)
    const int n_act = np + 8 * kh;
    float creg = 0.f;
    float* const yout = y + (size_t)(nb0 + n_act) * TT * HH + hc0 + j;
    const float* const xbase = g_xh + (size_t)(nb0 + n_act) * G4 + hc0 + j;

    float* const redw = &red[tid * 5];                 // my export slot
    const float* const redr = &red[(tid ^ 128) * 5];   // partner's slot

    unsigned* const myflag = &g_flag[b * FLAG_STRIDE];
    const int ws = warp - 8;               // stager warp index 0..3

    __syncthreads();

    for (int tstep = 0; tstep < TT; tstep++) {
        if (is_dot) {
            // ---- prefetch this step's input-projection gates (4 scalars)
            const float* xp = xbase + (size_t)tstep * NB * G4;
            const float xv0 = xp[0 * HH];
            const float xv1 = xp[1 * HH];
            const float xv2 = xp[2 * HH];
            const float xv3 = xp[3 * HH];

            // ---- dot: partial gates over this warp's k-half
            u64 a00 = 0ull, a01 = 0ull, a02 = 0ull, a03 = 0ull;  // n = np
            u64 a10 = 0ull, a11 = 0ull, a12 = 0ull, a13 = 0ull;  // n = np+8
            if (tstep > 0) {
                // wait for stagers: h(tstep-1) complete in hs[(tstep-1)&1]
                asm volatile("bar.sync 1, %0;" :: "n"(NTH) : "memory");

                const float* __restrict__ hb =
                    hs + ((tstep - 1) & 1) * SM_H1;
                const float* __restrict__ hr0 = hb + np * HSL + k0;
                const float* __restrict__ hr1 = hb + (np + 8) * HSL + k0;
                const float* __restrict__ wp0 = wsT + woff0;
                const float* __restrict__ wp1 = wsT + woff1;
                const float* __restrict__ wp2 = wsT + woff2;
                const float* __restrict__ wp3 = wsT + woff3;
#pragma unroll 8
                for (int k = 0; k < KHALF; k += 4) {
                    const ulonglong2 hp0 = *(const ulonglong2*)(hr0 + k);
                    const ulonglong2 hp1 = *(const ulonglong2*)(hr1 + k);
                    const ulonglong2 w0 = *(const ulonglong2*)(wp0 + k);
                    const ulonglong2 w1 = *(const ulonglong2*)(wp1 + k);
                    const ulonglong2 w2 = *(const ulonglong2*)(wp2 + k);
                    const ulonglong2 w3 = *(const ulonglong2*)(wp3 + k);
                    ffma2(a00, hp0.x, w0.x); ffma2(a00, hp0.y, w0.y);
                    ffma2(a01, hp0.x, w1.x); ffma2(a01, hp0.y, w1.y);
                    ffma2(a02, hp0.x, w2.x); ffma2(a02, hp0.y, w2.y);
                    ffma2(a03, hp0.x, w3.x); ffma2(a03, hp0.y, w3.y);
                    ffma2(a10, hp1.x, w0.x); ffma2(a10, hp1.y, w0.y);
                    ffma2(a11, hp1.x, w1.x); ffma2(a11, hp1.y, w1.y);
                    ffma2(a12, hp1.x, w2.x); ffma2(a12, hp1.y, w2.y);
                    ffma2(a13, hp1.x, w3.x); ffma2(a13, hp1.y, w3.y);
                }
            }

            // ---- horizontal reduce
            float s00, s01, s02, s03, s10, s11, s12, s13;
            {
                float2 t2;
                t2 = unpk(a00); s00 = t2.x + t2.y;
                t2 = unpk(a01); s01 = t2.x + t2.y;
                t2 = unpk(a02); s02 = t2.x + t2.y;
                t2 = unpk(a03); s03 = t2.x + t2.y;
                t2 = unpk(a10); s10 = t2.x + t2.y;
                t2 = unpk(a11); s11 = t2.x + t2.y;
                t2 = unpk(a12); s12 = t2.x + t2.y;
                t2 = unpk(a13); s13 = t2.x + t2.y;
            }

            // ---- export the half my partner consumes
            if (kh == 0) {
                redw[0] = s10; redw[1] = s11; redw[2] = s12; redw[3] = s13;
            } else {
                redw[0] = s00; redw[1] = s01; redw[2] = s02; redw[3] = s03;
            }
            asm volatile("bar.sync 2, 256;" ::: "memory");

            // ---- combine partner partials, activate, store
            {
                float m0, m1, m2, m3;
                if (kh == 0) { m0 = s00; m1 = s01; m2 = s02; m3 = s03; }
                else         { m0 = s10; m1 = s11; m2 = s12; m3 = s13; }
                const float gi = m0 + redr[0] + xv0;
                const float gf = m1 + redr[1] + xv1;
                const float gc = m2 + redr[2] + xv2;
                const float go = m3 + redr[3] + xv3;
                const float iv = fsigmoid_(gi);
                const float fv = fsigmoid_(gf);
                const float gv = ftanh_(gc);
                const float ov = fsigmoid_(go);
                creg = fv * creg + iv * gv;
                yout[(size_t)tstep * HH] = ov * ftanh_(creg);
            }
            asm volatile("bar.sync 2, 256;" ::: "memory");  // y stores + red reads done

            if (tstep < TT - 1 && tid == 0) {
                asm volatile("st.release.gpu.u32 [%0], %1;"
                             :: "l"(myflag), "r"((unsigned)(tstep + 1))
                             : "memory");
            }
        } else {
            // ================= stager warps (8-11) =================
            if (tstep < TT - 1) {
                // poll my 8 producers' flags (every lane acquires all 8)
                const unsigned want = (unsigned)(tstep + 1);
#pragma unroll
                for (int i = 0; i < 8; i++) {
                    unsigned* pf =
                        &g_flag[(((8 * ws + i) << 2) | bg) * FLAG_STRIDE];
                    unsigned v;
                    do {
                        asm volatile("ld.acquire.gpu.u32 %0, [%1];"
                                     : "=r"(v) : "l"(pf) : "memory");
                    } while (v < want);
                }

                // copy 16 rows x 128 cols (cols [128ws,128ws+128)) of h(t)
                float* __restrict__ dstb =
                    hs + (tstep & 1) * SM_H1 + 128 * ws;
#pragma unroll 4
                for (int i = 0; i < 16; i++) {
                    const float4* __restrict__ s = (const float4*)
                        (y + (size_t)(nb0 + i) * TT * HH
                           + (size_t)tstep * HH + 128 * ws);
                    float4* __restrict__ d = (float4*)(dstb + i * HSL);
                    d[lane] = s[lane];
                }
                asm volatile("bar.arrive 1, %0;" :: "n"(NTH) : "memory");
            }
        }
    }
}

// ---------------------------------------------------------------------------
// Launch
// ---------------------------------------------------------------------------
extern "C" void kernel_launch(void* const* d_in, const int* in_sizes, int n_in,
                              void* d_out, int out_size)
{
    const float* x   = (const float*)d_in[0];   // (64, 512, 512)
    const float* Wxh = (const float*)d_in[1];   // (512, 2048)
    const float* Whh = (const float*)d_in[2];   // (512, 2048)
    const float* bxh = (const float*)d_in[3];   // (2048,)
    const float* bhh = (const float*)d_in[4];   // (2048,)
    float* y = (float*)d_out;                   // (64, 512, 512)

    // opt-in to >48KB dynamic smem (idempotent host call, capture-safe)
    cudaFuncSetAttribute(lstm_kernel,
                         cudaFuncAttributeMaxDynamicSharedMemorySize, SM_BYTES);

    dim3 ggrid(G4 / BN, (TT * NB) / BM);        // (16, 256)
    gemm_xh_kernel<<<ggrid, 256>>>(x, Wxh, bxh, bhh);   // also resets flags

    lstm_kernel<<<NCTA, NTH, SM_BYTES>>>(Whh, y);
}